// round 13
// baseline (speedup 1.0000x reference)
#include <cuda_runtime.h>
#include <cuda_fp16.h>
#include <cstdint>
#include <math.h>

#define HID 256
#define SPB 4           // samples per tile -> M = 32 jet rows
#define TPB 128         // 4 warps, each m32 x n64 (ntq = wid)
#define NSM 148
#define BLKS (NSM * 4)  // persistent grid

#define RSA 528         // A smem row stride bytes (264 fp16: 256 + 8 pad)

// ---- dynamic smem offsets (bytes) ----
#define SM_RED   0                          // 128 floats
#define SM_JT    1024                       // 4 warps * 4KB: [zin 1K | h 1K | t 1K | c 1K]
#define SM_AH    (SM_JT + 16384)            // 17408
#define SM_AL    (SM_AH + 32 * RSA)         // 34304
#define SMEM_TOTAL (SM_AL + 32 * RSA)       // 51200 -> 4 blocks/SM

// W (fp16) pre-packed in exact m16n8k16 B-fragment layout:
// uint4 g_wfrag[(l*4 + ntq)*2048 + (ki*4+p)*32 + lane]
__device__ __align__(16) uint4 g_wfrag[3 * 4 * 2048];

// ---------------- helpers ----------------
__device__ __forceinline__ uint32_t smem_u32(const void* p) {
    uint32_t a;
    asm("{ .reg .u64 t; cvta.to.shared.u64 t, %1; cvt.u32.u64 %0, t; }" : "=r"(a) : "l"(p));
    return a;
}
__device__ __forceinline__ void ldsm_x4(uint32_t addr, uint32_t r[4]) {
    asm volatile("ldmatrix.sync.aligned.m8n8.x4.shared.b16 {%0,%1,%2,%3}, [%4];"
                 : "=r"(r[0]), "=r"(r[1]), "=r"(r[2]), "=r"(r[3]) : "r"(addr));
}
__device__ __forceinline__ void mma16816(float d[4], const uint32_t a[4],
                                         uint32_t b0, uint32_t b1) {
    asm volatile("mma.sync.aligned.m16n8k16.row.col.f32.f16.f16.f32 "
                 "{%0,%1,%2,%3},{%4,%5,%6,%7},{%8,%9},{%0,%1,%2,%3};"
                 : "+f"(d[0]), "+f"(d[1]), "+f"(d[2]), "+f"(d[3])
                 : "r"(a[0]), "r"(a[1]), "r"(a[2]), "r"(a[3]), "r"(b0), "r"(b1));
}
__device__ __forceinline__ float my_tanhf(float z) {
    float a = fabsf(z);
    float e = __expf(-2.0f * a);
    float t = __fdividef(1.0f - e, 1.0f + e);
    return copysignf(t, z);
}
// fp16 hi/lo exact 2-way split of two floats, packed as {v0,v1} half2 words
__device__ __forceinline__ void split_pack(float a, float b, uint32_t& hi, uint32_t& lo) {
    __half ha = __float2half_rn(a), hb = __float2half_rn(b);
    __half la = __float2half_rn(a - __half2float(ha));
    __half lb = __float2half_rn(b - __half2float(hb));
    hi = (uint32_t)__half_as_ushort(ha) | ((uint32_t)__half_as_ushort(hb) << 16);
    lo = (uint32_t)__half_as_ushort(la) | ((uint32_t)__half_as_ushort(lb) << 16);
}
__device__ __forceinline__ void storeA(char* smem, int m, int nc, float v0, float v1) {
    uint32_t hi, lo; split_pack(v0, v1, hi, lo);
    int off = m * RSA + nc * 2;
    *(uint32_t*)(smem + SM_AH + off) = hi;
    *(uint32_t*)(smem + SM_AL + off) = lo;
}

// ---------------- prep: W -> fp16 B-fragment layout ----------------
__global__ void prep_w_kernel(const float* __restrict__ W1, const float* __restrict__ W2,
                              const float* __restrict__ W3) {
    int idx = blockIdx.x * blockDim.x + threadIdx.x;
    if (idx >= 3 * 32768) return;
    int l    = idx >> 15;
    int rem  = idx & 32767;
    int nt16 = rem >> 11;
    int ki   = (rem >> 7) & 15;
    int r    = (rem >> 5) & 3;
    int lane = rem & 31;
    int n = nt16 * 16 + ((r >> 1) << 3) + (lane >> 2);
    int k = ki * 16 + ((r & 1) << 3) + ((lane & 3) << 1);
    const float* W = (l == 0) ? W1 : (l == 1) ? W2 : W3;
    float v0 = W[k * HID + n];
    float v1 = W[(k + 1) * HID + n];
    __half h0 = __float2half_rn(v0), h1 = __float2half_rn(v1);
    uint32_t hip = (uint32_t)__half_as_ushort(h0) | ((uint32_t)__half_as_ushort(h1) << 16);
    int ntq = nt16 >> 2, p = nt16 & 3;
    int slot = ((ki * 4 + p) * 32 + lane) * 4 + r;
    uint32_t* w32 = (uint32_t*)g_wfrag;
    w32[((l * 4 + ntq) * 2048) * 4 + slot] = hip;
}

// ---------------- main kernel (persistent) ----------------
__global__ __launch_bounds__(TPB, 4) void pinn_mma_kernel(
    const float* __restrict__ x,
    const float* __restrict__ W0, const float* __restrict__ b0,
    const float* __restrict__ b1, const float* __restrict__ b2,
    const float* __restrict__ b3,
    const float* __restrict__ Wout, const float* __restrict__ bout,
    float* __restrict__ out, int B, int ntiles)
{
    extern __shared__ char smem[];
    const uint32_t sb = smem_u32(smem);
    const int tid = threadIdx.x, wid = tid >> 5, lane = tid & 31;

    // layer-0 weights, loaded once per block
    const int nc = tid * 2;
    const float wa0 = __ldg(&W0[nc]),     wa1 = __ldg(&W0[HID + nc]),     wa2 = __ldg(&W0[2*HID + nc]);
    const float wb0 = __ldg(&W0[nc + 1]), wb1 = __ldg(&W0[HID + nc + 1]), wb2 = __ldg(&W0[2*HID + nc + 1]);
    const float ba = __ldg(&b0[nc]), bb = __ldg(&b0[nc + 1]);
    const float boutv = __ldg(&bout[0]);

    // warp tiling constants
    const int ntq = wid;
    const int ncol0 = ntq * 64;
    const int ch = lane >> 2;
    const int srcb = lane & 3;
    const uint32_t aOff = (uint32_t)((lane & 15) * RSA + (lane >> 4) * 16);
    char* zin = smem + SM_JT + wid * 4096;
    char* hpl = zin + 1024;
    char* tpl = zin + 2048;
    char* cpl = zin + 3072;

    for (int tile = blockIdx.x; tile < ntiles; tile += BLKS) {
        const int base = tile * SPB;

        // -------- layer 0: analytic jets -> A (rows m = s*8 + ch) --------
        #pragma unroll
        for (int s = 0; s < SPB; s++) {
            int idx = base + s; if (idx >= B) idx = B - 1;
            float x0 = __ldg(&x[idx*3]), x1 = __ldg(&x[idx*3+1]), x2 = __ldg(&x[idx*3+2]);
            float za = fmaf(x2, wa2, fmaf(x1, wa1, fmaf(x0, wa0, ba)));
            float zb = fmaf(x2, wb2, fmaf(x1, wb1, fmaf(x0, wb0, bb)));
            float hA = my_tanhf(za), tA = 1.f - hA*hA, cA = -2.f*hA*tA;
            float hB = my_tanhf(zb), tB = 1.f - hB*hB, cB = -2.f*hB*tB;
            float va[8] = {hA, tA*wa0, tA*wa1, tA*wa2, cA*wa0*wa0, cA*wa1*wa1, cA*wa2*wa2, 0.f};
            float vb[8] = {hB, tB*wb0, tB*wb1, tB*wb2, cB*wb0*wb0, cB*wb1*wb1, cB*wb2*wb2, 0.f};
            #pragma unroll
            for (int c = 0; c < 8; c++) storeA(smem, s * 8 + c, nc, va[c], vb[c]);
        }
        __syncthreads();

        #pragma unroll 1
        for (int l = 0; l < 3; l++) {
            float acc[2][8][4];
            #pragma unroll
            for (int t = 0; t < 2; t++)
                #pragma unroll
                for (int nt = 0; nt < 8; nt++)
                    { acc[t][nt][0]=0.f; acc[t][nt][1]=0.f; acc[t][nt][2]=0.f; acc[t][nt][3]=0.f; }

            const uint4* fH = g_wfrag + (uint32_t)(l * 4 + ntq) * 2048 + lane;

            // B frags: register double buffer (prefetch ki+1 before ki's MMAs)
            uint4 bcur[4], bnxt[4];
            #pragma unroll
            for (int p = 0; p < 4; p++) bcur[p] = __ldg(fH + p * 32);

            #pragma unroll
            for (int ki = 0; ki < 16; ki++) {
                if (ki < 15) {
                    #pragma unroll
                    for (int p = 0; p < 4; p++)
                        bnxt[p] = __ldg(fH + ((ki + 1) * 4 + p) * 32);
                }
                uint32_t ah[2][4], al[2][4];
                const uint32_t akb = (uint32_t)(ki * 32);
                #pragma unroll
                for (int t = 0; t < 2; t++) {
                    ldsm_x4(sb + SM_AH + aOff + (uint32_t)(t * 16 * RSA) + akb, ah[t]);
                    ldsm_x4(sb + SM_AL + aOff + (uint32_t)(t * 16 * RSA) + akb, al[t]);
                }
                #pragma unroll
                for (int p = 0; p < 4; p++)
                    #pragma unroll
                    for (int t = 0; t < 2; t++) {
                        mma16816(acc[t][2*p],   ah[t], bcur[p].x, bcur[p].y);
                        mma16816(acc[t][2*p+1], ah[t], bcur[p].z, bcur[p].w);
                    }
                #pragma unroll
                for (int p = 0; p < 4; p++)
                    #pragma unroll
                    for (int t = 0; t < 2; t++) {
                        mma16816(acc[t][2*p],   al[t], bcur[p].x, bcur[p].y);
                        mma16816(acc[t][2*p+1], al[t], bcur[p].z, bcur[p].w);
                    }
                #pragma unroll
                for (int p = 0; p < 4; p++) bcur[p] = bnxt[p];
            }
            __syncthreads();   // all MMA reads of A done before epilogue overwrites A

            // -------- pass A: lanes 0-3 dump h-channel z rows to zin ----
            if (ch == 0) {
                #pragma unroll
                for (int t = 0; t < 2; t++)
                    #pragma unroll
                    for (int nt = 0; nt < 8; nt++) {
                        int cq = nt * 8 + srcb * 2;
                        *(float2*)(zin + ((t*2    ) * 64 + cq) * 4) =
                            make_float2(acc[t][nt][0], acc[t][nt][1]);
                        *(float2*)(zin + ((t*2 + 1) * 64 + cq) * 4) =
                            make_float2(acc[t][nt][2], acc[t][nt][3]);
                    }
            }
            __syncwarp();

            // -------- pass B: 8 distinct tanh per lane --------
            const float* bp = (l == 0) ? b1 : (l == 1) ? b2 : b3;
            {
                const int vb = lane * 4;
                float4 za = *(float4*)(zin + vb * 4);
                float4 zb4 = *(float4*)(zin + (vb + 128) * 4);
                float4 bi = __ldg((const float4*)(bp + ncol0) + (lane & 15));
                float h0 = my_tanhf(za.x + bi.x), h1 = my_tanhf(za.y + bi.y);
                float h2 = my_tanhf(za.z + bi.z), h3 = my_tanhf(za.w + bi.w);
                float h4 = my_tanhf(zb4.x + bi.x), h5 = my_tanhf(zb4.y + bi.y);
                float h6 = my_tanhf(zb4.z + bi.z), h7 = my_tanhf(zb4.w + bi.w);
                float t0 = 1.f-h0*h0, t1 = 1.f-h1*h1, t2 = 1.f-h2*h2, t3 = 1.f-h3*h3;
                float t4 = 1.f-h4*h4, t5 = 1.f-h5*h5, t6 = 1.f-h6*h6, t7 = 1.f-h7*h7;
                *(float4*)(hpl + vb * 4)         = make_float4(h0, h1, h2, h3);
                *(float4*)(hpl + (vb + 128) * 4) = make_float4(h4, h5, h6, h7);
                *(float4*)(tpl + vb * 4)         = make_float4(t0, t1, t2, t3);
                *(float4*)(tpl + (vb + 128) * 4) = make_float4(t4, t5, t6, t7);
                *(float4*)(cpl + vb * 4)         = make_float4(-2.f*h0*t0, -2.f*h1*t1, -2.f*h2*t2, -2.f*h3*t3);
                *(float4*)(cpl + (vb + 128) * 4) = make_float4(-2.f*h4*t4, -2.f*h5*t5, -2.f*h6*t6, -2.f*h7*t7);
            }
            __syncwarp();

            // -------- pass C: jet transform (tanh-free) ----------
            float accO[2][2] = {{0.f, 0.f}, {0.f, 0.f}};
            const int gsrc = (lane - 12) & 31;
            const char* sp = (ch == 0) ? hpl : tpl;

            #pragma unroll
            for (int t = 0; t < 2; t++) {
                #pragma unroll
                for (int nt = 0; nt < 8; nt++) {
                    int cq   = nt * 8 + (srcb << 1);
                    int ncol = ncol0 + cq;
                    float z0 = acc[t][nt][0], z1 = acc[t][nt][1];
                    float z2 = acc[t][nt][2], z3 = acc[t][nt][3];
                    float2 pA = *(float2*)(sp  + ((t*2    ) * 64 + cq) * 4);
                    float2 pB = *(float2*)(sp  + ((t*2 + 1) * 64 + cq) * 4);
                    float2 qA = *(float2*)(cpl + ((t*2    ) * 64 + cq) * 4);
                    float2 qB = *(float2*)(cpl + ((t*2 + 1) * 64 + cq) * 4);
                    float zg0 = __shfl_sync(0xffffffffu, z0, gsrc);
                    float zg1 = __shfl_sync(0xffffffffu, z1, gsrc);
                    float zg2 = __shfl_sync(0xffffffffu, z2, gsrc);
                    float zg3 = __shfl_sync(0xffffffffu, z3, gsrc);
                    float o0 = (ch == 0) ? pA.x : (ch < 4) ? pA.x * z0
                             : (ch < 7) ? fmaf(qA.x * zg0, zg0, pA.x * z0) : 0.f;
                    float o1 = (ch == 0) ? pA.y : (ch < 4) ? pA.y * z1
                             : (ch < 7) ? fmaf(qA.y * zg1, zg1, pA.y * z1) : 0.f;
                    float o2 = (ch == 0) ? pB.x : (ch < 4) ? pB.x * z2
                             : (ch < 7) ? fmaf(qB.x * zg2, zg2, pB.x * z2) : 0.f;
                    float o3 = (ch == 0) ? pB.y : (ch < 4) ? pB.y * z3
                             : (ch < 7) ? fmaf(qB.y * zg3, zg3, pB.y * z3) : 0.f;
                    if (l < 2) {
                        storeA(smem, t * 16 + ch,     ncol, o0, o1);
                        storeA(smem, t * 16 + ch + 8, ncol, o2, o3);
                    } else {
                        float w0 = __ldg(&Wout[ncol]), w1 = __ldg(&Wout[ncol + 1]);
                        accO[t][0] = fmaf(o0, w0, fmaf(o1, w1, accO[t][0]));
                        accO[t][1] = fmaf(o2, w0, fmaf(o3, w1, accO[t][1]));
                    }
                }
            }

            if (l < 2) {
                __syncthreads();   // A stores visible before next layer's LDSM
            } else {
                #pragma unroll
                for (int t = 0; t < 2; t++) {
                    accO[t][0] += __shfl_xor_sync(0xffffffffu, accO[t][0], 1);
                    accO[t][0] += __shfl_xor_sync(0xffffffffu, accO[t][0], 2);
                    accO[t][1] += __shfl_xor_sync(0xffffffffu, accO[t][1], 1);
                    accO[t][1] += __shfl_xor_sync(0xffffffffu, accO[t][1], 2);
                }
                float* red = (float*)(smem + SM_RED);
                if (srcb == 0) {
                    #pragma unroll
                    for (int t = 0; t < 2; t++) {
                        red[ntq * 32 + t * 16 + ch]     = accO[t][0];
                        red[ntq * 32 + t * 16 + ch + 8] = accO[t][1];
                    }
                }
                __syncthreads();
                if (tid < 32) {
                    float v = red[tid] + red[32 + tid] + red[64 + tid] + red[96 + tid];
                    int s = tid >> 3, c = tid & 7;
                    int g = base + s;
                    if (c < 7 && g < B) {
                        if (c == 0) v += boutv;
                        out[g * 7 + c] = v;
                    }
                }
                __syncthreads();   // red reads done before next tile reuses smem
            }
        }
    }
}

extern "C" void kernel_launch(void* const* d_in, const int* in_sizes, int n_in,
                              void* d_out, int out_size)
{
    const float* x    = (const float*)d_in[0];
    const float* W0   = (const float*)d_in[1];
    const float* b0   = (const float*)d_in[2];
    const float* W1   = (const float*)d_in[3];
    const float* b1   = (const float*)d_in[4];
    const float* W2   = (const float*)d_in[5];
    const float* b2   = (const float*)d_in[6];
    const float* W3   = (const float*)d_in[7];
    const float* b3   = (const float*)d_in[8];
    const float* Wout = (const float*)d_in[9];
    const float* bout = (const float*)d_in[10];
    float* out = (float*)d_out;

    const int B = in_sizes[0] / 3;
    const int ntiles = (B + SPB - 1) / SPB;

    prep_w_kernel<<<(3 * 32768 + 255) / 256, 256>>>(W1, W2, W3);

    cudaFuncSetAttribute(pinn_mma_kernel,
                         cudaFuncAttributeMaxDynamicSharedMemorySize, SMEM_TOTAL);
    pinn_mma_kernel<<<BLKS, TPB, SMEM_TOTAL>>>(x, W0, b0, b1, b2, b3,
                                               Wout, bout, out, B, ntiles);
}

// round 14
// speedup vs baseline: 1.0749x; 1.0749x over previous
#include <cuda_runtime.h>
#include <cuda_fp16.h>
#include <cstdint>
#include <math.h>

#define HID 256
#define SPB 4           // samples per block -> M = 32 jet rows
#define TPB 128         // 4 warps, each m32 x n64 (ntq = wid)

#define RSA 528         // A smem row stride bytes (264 fp16: 256 + 8 pad)

// ---- dynamic smem offsets (bytes) ----
#define SM_RED   0                          // 128 floats
#define SM_JT    1024                       // 4 warps * 4KB: [zin 1K | h 1K | t 1K | c 1K]
#define SM_AH    (SM_JT + 16384)            // 17408
#define SM_AL    (SM_AH + 32 * RSA)         // 34304
#define SMEM_TOTAL (SM_AL + 32 * RSA)       // 51200 -> 4 blocks/SM

// W (fp16) pre-packed in exact m16n8k16 B-fragment layout:
// uint4 g_wfrag[(l*4 + ntq)*2048 + (ki*4+p)*32 + lane]
__device__ __align__(16) uint4 g_wfrag[3 * 4 * 2048];

// ---------------- helpers ----------------
__device__ __forceinline__ uint32_t smem_u32(const void* p) {
    uint32_t a;
    asm("{ .reg .u64 t; cvta.to.shared.u64 t, %1; cvt.u32.u64 %0, t; }" : "=r"(a) : "l"(p));
    return a;
}
__device__ __forceinline__ void ldsm_x4(uint32_t addr, uint32_t r[4]) {
    asm volatile("ldmatrix.sync.aligned.m8n8.x4.shared.b16 {%0,%1,%2,%3}, [%4];"
                 : "=r"(r[0]), "=r"(r[1]), "=r"(r[2]), "=r"(r[3]) : "r"(addr));
}
__device__ __forceinline__ void mma16816(float d[4], const uint32_t a[4],
                                         uint32_t b0, uint32_t b1) {
    asm volatile("mma.sync.aligned.m16n8k16.row.col.f32.f16.f16.f32 "
                 "{%0,%1,%2,%3},{%4,%5,%6,%7},{%8,%9},{%0,%1,%2,%3};"
                 : "+f"(d[0]), "+f"(d[1]), "+f"(d[2]), "+f"(d[3])
                 : "r"(a[0]), "r"(a[1]), "r"(a[2]), "r"(a[3]), "r"(b0), "r"(b1));
}
__device__ __forceinline__ float my_tanhf(float z) {
    float a = fabsf(z);
    float e = __expf(-2.0f * a);
    float t = __fdividef(1.0f - e, 1.0f + e);
    return copysignf(t, z);
}
// fp16 hi/lo exact 2-way split of two floats via packed f16x2 converts
__device__ __forceinline__ void split_pack(float a, float b, uint32_t& hi, uint32_t& lo) {
    __half2 h = __floats2half2_rn(a, b);           // 1x cvt.rn.f16x2.f32
    float2 hf = __half22float2(h);                 // 2x cvt.f32.f16
    __half2 l = __floats2half2_rn(a - hf.x, b - hf.y);
    hi = *(uint32_t*)&h;
    lo = *(uint32_t*)&l;
}
__device__ __forceinline__ void storeA(char* smem, int m, int nc, float v0, float v1) {
    uint32_t hi, lo; split_pack(v0, v1, hi, lo);
    int off = m * RSA + nc * 2;
    *(uint32_t*)(smem + SM_AH + off) = hi;
    *(uint32_t*)(smem + SM_AL + off) = lo;
}

// ---------------- prep: W -> fp16 B-fragment layout ----------------
__global__ void prep_w_kernel(const float* __restrict__ W1, const float* __restrict__ W2,
                              const float* __restrict__ W3) {
    int idx = blockIdx.x * blockDim.x + threadIdx.x;
    if (idx >= 3 * 32768) return;
    int l    = idx >> 15;
    int rem  = idx & 32767;
    int nt16 = rem >> 11;
    int ki   = (rem >> 7) & 15;
    int r    = (rem >> 5) & 3;
    int lane = rem & 31;
    int n = nt16 * 16 + ((r >> 1) << 3) + (lane >> 2);
    int k = ki * 16 + ((r & 1) << 3) + ((lane & 3) << 1);
    const float* W = (l == 0) ? W1 : (l == 1) ? W2 : W3;
    float v0 = W[k * HID + n];
    float v1 = W[(k + 1) * HID + n];
    __half h0 = __float2half_rn(v0), h1 = __float2half_rn(v1);
    uint32_t hip = (uint32_t)__half_as_ushort(h0) | ((uint32_t)__half_as_ushort(h1) << 16);
    int ntq = nt16 >> 2, p = nt16 & 3;
    int slot = ((ki * 4 + p) * 32 + lane) * 4 + r;
    uint32_t* w32 = (uint32_t*)g_wfrag;
    w32[((l * 4 + ntq) * 2048) * 4 + slot] = hip;
}

// ---------------- main kernel ----------------
__global__ __launch_bounds__(TPB, 4) void pinn_mma_kernel(
    const float* __restrict__ x,
    const float* __restrict__ W0, const float* __restrict__ b0,
    const float* __restrict__ b1, const float* __restrict__ b2,
    const float* __restrict__ b3,
    const float* __restrict__ Wout, const float* __restrict__ bout,
    float* __restrict__ out, int B)
{
    extern __shared__ char smem[];
    const uint32_t sb = smem_u32(smem);
    const int tid = threadIdx.x, wid = tid >> 5, lane = tid & 31;
    const int base = blockIdx.x * SPB;

    // -------- layer 0: analytic jets -> A (rows m = s*8 + ch) --------
    {
        const int nc = tid * 2;   // 128 threads cover 256 columns
        float wa0 = __ldg(&W0[nc]),     wa1 = __ldg(&W0[HID + nc]),     wa2 = __ldg(&W0[2*HID + nc]);
        float wb0 = __ldg(&W0[nc + 1]), wb1 = __ldg(&W0[HID + nc + 1]), wb2 = __ldg(&W0[2*HID + nc + 1]);
        float ba = __ldg(&b0[nc]), bb = __ldg(&b0[nc + 1]);
        #pragma unroll
        for (int s = 0; s < SPB; s++) {
            int idx = base + s; if (idx >= B) idx = B - 1;
            float x0 = __ldg(&x[idx*3]), x1 = __ldg(&x[idx*3+1]), x2 = __ldg(&x[idx*3+2]);
            float za = fmaf(x2, wa2, fmaf(x1, wa1, fmaf(x0, wa0, ba)));
            float zb = fmaf(x2, wb2, fmaf(x1, wb1, fmaf(x0, wb0, bb)));
            float hA = my_tanhf(za), tA = 1.f - hA*hA, cA = -2.f*hA*tA;
            float hB = my_tanhf(zb), tB = 1.f - hB*hB, cB = -2.f*hB*tB;
            float va[8] = {hA, tA*wa0, tA*wa1, tA*wa2, cA*wa0*wa0, cA*wa1*wa1, cA*wa2*wa2, 0.f};
            float vb[8] = {hB, tB*wb0, tB*wb1, tB*wb2, cB*wb0*wb0, cB*wb1*wb1, cB*wb2*wb2, 0.f};
            #pragma unroll
            for (int c = 0; c < 8; c++) storeA(smem, s * 8 + c, nc, va[c], vb[c]);
        }
    }
    __syncthreads();

    // warp tiling: each warp = m32 x n64, ntq = wid (4 warps cover n256)
    const int ntq = wid;
    const int ncol0 = ntq * 64;
    const int ch = lane >> 2;
    const int srcb = lane & 3;
    const uint32_t aOff = (uint32_t)((lane & 15) * RSA + (lane >> 4) * 16);
    // per-warp jet scratch: zin / h / t / c planes (1KB each)
    char* zin = smem + SM_JT + wid * 4096;
    char* hpl = zin + 1024;
    char* tpl = zin + 2048;
    char* cpl = zin + 3072;

    #pragma unroll 1
    for (int l = 0; l < 3; l++) {
        float acc[2][8][4];
        #pragma unroll
        for (int t = 0; t < 2; t++)
            #pragma unroll
            for (int nt = 0; nt < 8; nt++)
                { acc[t][nt][0]=0.f; acc[t][nt][1]=0.f; acc[t][nt][2]=0.f; acc[t][nt][3]=0.f; }

        const uint4* fH = g_wfrag + (uint32_t)(l * 4 + ntq) * 2048 + lane;

        #pragma unroll 8
        for (int ki = 0; ki < 16; ki++) {
            uint32_t ah[2][4], al[2][4];
            const uint32_t akb = (uint32_t)(ki * 32);
            #pragma unroll
            for (int t = 0; t < 2; t++) {
                ldsm_x4(sb + SM_AH + aOff + (uint32_t)(t * 16 * RSA) + akb, ah[t]);
                ldsm_x4(sb + SM_AL + aOff + (uint32_t)(t * 16 * RSA) + akb, al[t]);
            }
            uint4 bh[4];
            #pragma unroll
            for (int p = 0; p < 4; p++)
                bh[p] = __ldg(fH + (ki * 4 + p) * 32);
            #pragma unroll
            for (int p = 0; p < 4; p++)
                #pragma unroll
                for (int t = 0; t < 2; t++) {
                    mma16816(acc[t][2*p],   ah[t], bh[p].x, bh[p].y);
                    mma16816(acc[t][2*p+1], ah[t], bh[p].z, bh[p].w);
                }
            #pragma unroll
            for (int p = 0; p < 4; p++)
                #pragma unroll
                for (int t = 0; t < 2; t++) {
                    mma16816(acc[t][2*p],   al[t], bh[p].x, bh[p].y);
                    mma16816(acc[t][2*p+1], al[t], bh[p].z, bh[p].w);
                }
        }
        __syncthreads();   // all MMA reads of A done before epilogue overwrites A

        // -------- pass A: lanes 0-3 dump h-channel z rows to zin[s][col] ----
        if (ch == 0) {
            #pragma unroll
            for (int t = 0; t < 2; t++)
                #pragma unroll
                for (int nt = 0; nt < 8; nt++) {
                    int cq = nt * 8 + srcb * 2;
                    *(float2*)(zin + ((t*2    ) * 64 + cq) * 4) =
                        make_float2(acc[t][nt][0], acc[t][nt][1]);
                    *(float2*)(zin + ((t*2 + 1) * 64 + cq) * 4) =
                        make_float2(acc[t][nt][2], acc[t][nt][3]);
                }
        }
        __syncwarp();

        // -------- pass B: 8 distinct tanh per lane --------
        const float* bp = (l == 0) ? b1 : (l == 1) ? b2 : b3;
        {
            const int vb = lane * 4;
            float4 za = *(float4*)(zin + vb * 4);
            float4 zb4 = *(float4*)(zin + (vb + 128) * 4);
            float4 bi = __ldg((const float4*)(bp + ncol0) + (lane & 15));
            float h0 = my_tanhf(za.x + bi.x), h1 = my_tanhf(za.y + bi.y);
            float h2 = my_tanhf(za.z + bi.z), h3 = my_tanhf(za.w + bi.w);
            float h4 = my_tanhf(zb4.x + bi.x), h5 = my_tanhf(zb4.y + bi.y);
            float h6 = my_tanhf(zb4.z + bi.z), h7 = my_tanhf(zb4.w + bi.w);
            float t0 = 1.f-h0*h0, t1 = 1.f-h1*h1, t2 = 1.f-h2*h2, t3 = 1.f-h3*h3;
            float t4 = 1.f-h4*h4, t5 = 1.f-h5*h5, t6 = 1.f-h6*h6, t7 = 1.f-h7*h7;
            *(float4*)(hpl + vb * 4)         = make_float4(h0, h1, h2, h3);
            *(float4*)(hpl + (vb + 128) * 4) = make_float4(h4, h5, h6, h7);
            *(float4*)(tpl + vb * 4)         = make_float4(t0, t1, t2, t3);
            *(float4*)(tpl + (vb + 128) * 4) = make_float4(t4, t5, t6, t7);
            *(float4*)(cpl + vb * 4)         = make_float4(-2.f*h0*t0, -2.f*h1*t1, -2.f*h2*t2, -2.f*h3*t3);
            *(float4*)(cpl + (vb + 128) * 4) = make_float4(-2.f*h4*t4, -2.f*h5*t5, -2.f*h6*t6, -2.f*h7*t7);
        }
        __syncwarp();

        // -------- pass C: jet transform (tanh-free) ----------
        float accO[2][2] = {{0.f, 0.f}, {0.f, 0.f}};
        const int gsrc = (lane - 12) & 31;
        const char* sp = (ch == 0) ? hpl : tpl;

        #pragma unroll
        for (int t = 0; t < 2; t++) {
            #pragma unroll
            for (int nt = 0; nt < 8; nt++) {
                int cq   = nt * 8 + (srcb << 1);
                int ncol = ncol0 + cq;
                float z0 = acc[t][nt][0], z1 = acc[t][nt][1];
                float z2 = acc[t][nt][2], z3 = acc[t][nt][3];
                float2 pA = *(float2*)(sp  + ((t*2    ) * 64 + cq) * 4);
                float2 pB = *(float2*)(sp  + ((t*2 + 1) * 64 + cq) * 4);
                float2 qA = *(float2*)(cpl + ((t*2    ) * 64 + cq) * 4);
                float2 qB = *(float2*)(cpl + ((t*2 + 1) * 64 + cq) * 4);
                float zg0 = __shfl_sync(0xffffffffu, z0, gsrc);
                float zg1 = __shfl_sync(0xffffffffu, z1, gsrc);
                float zg2 = __shfl_sync(0xffffffffu, z2, gsrc);
                float zg3 = __shfl_sync(0xffffffffu, z3, gsrc);
                float o0 = (ch == 0) ? pA.x : (ch < 4) ? pA.x * z0
                         : (ch < 7) ? fmaf(qA.x * zg0, zg0, pA.x * z0) : 0.f;
                float o1 = (ch == 0) ? pA.y : (ch < 4) ? pA.y * z1
                         : (ch < 7) ? fmaf(qA.y * zg1, zg1, pA.y * z1) : 0.f;
                float o2 = (ch == 0) ? pB.x : (ch < 4) ? pB.x * z2
                         : (ch < 7) ? fmaf(qB.x * zg2, zg2, pB.x * z2) : 0.f;
                float o3 = (ch == 0) ? pB.y : (ch < 4) ? pB.y * z3
                         : (ch < 7) ? fmaf(qB.y * zg3, zg3, pB.y * z3) : 0.f;
                if (l < 2) {
                    storeA(smem, t * 16 + ch,     ncol, o0, o1);
                    storeA(smem, t * 16 + ch + 8, ncol, o2, o3);
                } else {
                    float w0 = __ldg(&Wout[ncol]), w1 = __ldg(&Wout[ncol + 1]);
                    accO[t][0] = fmaf(o0, w0, fmaf(o1, w1, accO[t][0]));
                    accO[t][1] = fmaf(o2, w0, fmaf(o3, w1, accO[t][1]));
                }
            }
        }

        if (l < 2) {
            __syncthreads();   // A stores visible before next layer's LDSM
        } else {
            #pragma unroll
            for (int t = 0; t < 2; t++) {
                accO[t][0] += __shfl_xor_sync(0xffffffffu, accO[t][0], 1);
                accO[t][0] += __shfl_xor_sync(0xffffffffu, accO[t][0], 2);
                accO[t][1] += __shfl_xor_sync(0xffffffffu, accO[t][1], 1);
                accO[t][1] += __shfl_xor_sync(0xffffffffu, accO[t][1], 2);
            }
            float* red = (float*)(smem + SM_RED);
            if (srcb == 0) {
                #pragma unroll
                for (int t = 0; t < 2; t++) {
                    red[ntq * 32 + t * 16 + ch]     = accO[t][0];
                    red[ntq * 32 + t * 16 + ch + 8] = accO[t][1];
                }
            }
            __syncthreads();
            if (tid < 32) {
                float v = red[tid] + red[32 + tid] + red[64 + tid] + red[96 + tid];
                int s = tid >> 3, c = tid & 7;
                int g = base + s;
                if (c < 7 && g < B) {
                    if (c == 0) v += __ldg(&bout[0]);
                    out[g * 7 + c] = v;
                }
            }
        }
    }
}

extern "C" void kernel_launch(void* const* d_in, const int* in_sizes, int n_in,
                              void* d_out, int out_size)
{
    const float* x    = (const float*)d_in[0];
    const float* W0   = (const float*)d_in[1];
    const float* b0   = (const float*)d_in[2];
    const float* W1   = (const float*)d_in[3];
    const float* b1   = (const float*)d_in[4];
    const float* W2   = (const float*)d_in[5];
    const float* b2   = (const float*)d_in[6];
    const float* W3   = (const float*)d_in[7];
    const float* b3   = (const float*)d_in[8];
    const float* Wout = (const float*)d_in[9];
    const float* bout = (const float*)d_in[10];
    float* out = (float*)d_out;

    const int B = in_sizes[0] / 3;
    const int nblk = (B + SPB - 1) / SPB;

    prep_w_kernel<<<(3 * 32768 + 255) / 256, 256>>>(W1, W2, W3);

    cudaFuncSetAttribute(pinn_mma_kernel,
                         cudaFuncAttributeMaxDynamicSharedMemorySize, SMEM_TOTAL);
    pinn_mma_kernel<<<nblk, TPB, SMEM_TOTAL>>>(x, W0, b0, b1, b2, b3,
                                               Wout, bout, out, B);
}